// round 16
// baseline (speedup 1.0000x reference)
#include <cuda_runtime.h>
#include <cuda_fp16.h>
#include <cstdint>

#define NB     64
#define EMB    512
#define HID    1024
#define LSEQ   512
#define TSTEPS 511

#define NSTAGE        3
#define A_STAGE_HALFS 4096          // 64x64 half = 8192 B
#define W_CHUNK_HALFS 3072          // 48x64 half = 6144 B
#define SM_W_OFF      24576         // bytes: weight region after 3 A stages
#define SM_TOTAL      (24576 + 48 * 2048 * 2)   // 221184 B

// -------- device global scratch (allocation-free rule) --------
__device__ __align__(16) __half g_X[(size_t)TSTEPS * NB * EMB]; // [t][n][k]
__device__ __align__(16) __half g_B0[3072 * 1536];              // row j: [Wih0 | Whh0]
__device__ __align__(16) __half g_B1[3072 * 2048];              // row j: [Wih1 | Whh1]
__device__ __align__(16) float  g_h0f[2][NB * HID];
__device__ __align__(16) float  g_h1f[2][NB * HID];
__device__ __align__(16) __half g_h0h[2][NB * HID];
__device__ __align__(16) __half g_h1h[2][NB * HID];
__device__ int g_bar_cnt;

// -------- PTX helpers --------
__device__ __forceinline__ void cp_async16(void* s, const void* g) {
    uint32_t sa = (uint32_t)__cvta_generic_to_shared(s);
    asm volatile("cp.async.cg.shared.global [%0], [%1], 16;\n" :: "r"(sa), "l"(g));
}
__device__ __forceinline__ void ldsm4(uint32_t& r0, uint32_t& r1, uint32_t& r2, uint32_t& r3,
                                      const void* p) {
    uint32_t a = (uint32_t)__cvta_generic_to_shared(p);
    asm volatile("ldmatrix.sync.aligned.m8n8.x4.shared.b16 {%0,%1,%2,%3}, [%4];\n"
                 : "=r"(r0), "=r"(r1), "=r"(r2), "=r"(r3) : "r"(a));
}
__device__ __forceinline__ void mma_fp16(float (&d)[4], uint32_t a0, uint32_t a1, uint32_t a2,
                                         uint32_t a3, uint32_t b0, uint32_t b1) {
    asm volatile(
        "mma.sync.aligned.m16n8k16.row.col.f32.f16.f16.f32 "
        "{%0,%1,%2,%3},{%4,%5,%6,%7},{%8,%9},{%0,%1,%2,%3};\n"
        : "+f"(d[0]), "+f"(d[1]), "+f"(d[2]), "+f"(d[3])
        : "r"(a0), "r"(a1), "r"(a2), "r"(a3), "r"(b0), "r"(b1));
}

// -------- one-time (per replay) prep kernels --------
__global__ void k_init(const float* __restrict__ dec_init) {
    if (blockIdx.x == 0 && threadIdx.x == 0) g_bar_cnt = 0;
    for (int i = blockIdx.x * blockDim.x + threadIdx.x; i < NB * HID;
         i += gridDim.x * blockDim.x) {
        float v0 = dec_init[i];
        float v1 = dec_init[NB * HID + i];
        g_h0f[0][i] = v0; g_h0h[0][i] = __float2half(v0);
        g_h1f[0][i] = v1; g_h1h[0][i] = __float2half(v1);
    }
}

__global__ void k_pack(const float* __restrict__ Wih0, const float* __restrict__ Whh0,
                       const float* __restrict__ Wih1, const float* __restrict__ Whh1) {
    const int N0 = 3072 * 1536;
    const int N1 = 3072 * 2048;
    for (int i = blockIdx.x * blockDim.x + threadIdx.x; i < N0 + N1;
         i += gridDim.x * blockDim.x) {
        if (i < N0) {
            int j = i / 1536, k = i % 1536;
            float v = (k < 512) ? Wih0[(size_t)j * 512 + k] : Whh0[(size_t)j * 1024 + (k - 512)];
            g_B0[i] = __float2half(v);
        } else {
            int ii = i - N0;
            int j = ii >> 11, k = ii & 2047;
            float v = (k < 1024) ? Wih1[(size_t)j * 1024 + k] : Whh1[(size_t)j * 1024 + (k - 1024)];
            g_B1[ii] = __float2half(v);
        }
    }
}

__global__ void k_embed(const int* __restrict__ tokens, const float* __restrict__ emb) {
    int tn = blockIdx.x;          // t*64 + n
    int t = tn >> 6, n = tn & 63;
    int tok = tokens[n * LSEQ + t];      // tokens[:, :-1] -> col t < 511
    const float* src = emb + (size_t)tok * EMB;
    __half* dst = g_X + (size_t)tn * EMB;
    for (int k = threadIdx.x; k < EMB; k += blockDim.x)
        dst[k] = __float2half(src[k]);
}

__global__ void k_final(float* __restrict__ out) {
    size_t base = (size_t)NB * TSTEPS * HID;
    for (int i = blockIdx.x * blockDim.x + threadIdx.x; i < NB * HID;
         i += gridDim.x * blockDim.x) {
        out[base + i] = g_h0f[1][i];                // 511 steps -> final parity buffer = 1
        out[base + NB * HID + i] = g_h1f[1][i];
    }
}

// -------- A-chunk stage loader (cp.async -> ring slot) --------
__device__ __forceinline__ void load_A(int c, int slot, int tid,
                                       const __half* A0, int sA0, int kA0,
                                       const __half* A1, unsigned char* smraw) {
    __half* dA = (__half*)smraw + slot * A_STAGE_HALFS;
    const int kbase = c << 6;
    {
        int idx = tid; int row = idx >> 3, c16 = idx & 7;
        int k = kbase + c16 * 8;
        const __half* s = (k < kA0) ? (A0 + (size_t)row * sA0 + k)
                                    : (A1 + (size_t)row * HID + (k - kA0));
        cp_async16(dA + row * 64 + ((c16 ^ (row & 7)) << 3), s);
    }
    if (tid < 128) {
        int idx = tid + 384; int row = idx >> 3, c16 = idx & 7;
        int k = kbase + c16 * 8;
        const __half* s = (k < kA0) ? (A0 + (size_t)row * sA0 + k)
                                    : (A1 + (size_t)row * HID + (k - kA0));
        cp_async16(dA + row * 64 + ((c16 ^ (row & 7)) << 3), s);
    }
    asm volatile("cp.async.commit_group;\n" ::: "memory");
}

// -------- grid barrier (all 128 CTAs resident; monotonic counter, no ABA) --------
__device__ __forceinline__ void grid_bar(int target) {
    __threadfence();          // every thread: flush its h-state STGs device-wide
    __syncthreads();
    if (threadIdx.x == 0) {
        atomicAdd(&g_bar_cnt, 1);
        while (*(volatile int*)&g_bar_cnt < target) __nanosleep(64);
        __threadfence();
    }
    __syncthreads();
}

// -------- persistent kernel: 128 CTAs, weights SMEM-resident, 512 waves --------
// CTAs 0-63: layer0 tile jblk (16 units); CTAs 64-127: layer1 tile. Wave w runs
// L0(step w) and L1(step w-1) concurrently (disjoint parity buffers), separated
// from the next wave by the grid barrier. Cross-CTA h reads go through
// cp.async.cg (L2) -> no stale-L1 hazard; f32 h_old reads are CTA-own columns.
__global__ __launch_bounds__(384, 1) void k_run(const float* __restrict__ bih0,
                                                const float* __restrict__ bhh0,
                                                const float* __restrict__ bih1,
                                                const float* __restrict__ bhh1,
                                                float* __restrict__ out) {
    extern __shared__ __align__(16) unsigned char smraw[];
    const int tid = threadIdx.x;
    const int wid = tid >> 5;
    const int lane = tid & 31;
    const int wm = wid & 3;       // M tile 0-3
    const int ng = wid >> 2;      // N16 tile 0-2
    const int role = (blockIdx.x < 64) ? 0 : 1;
    const int jblk = role ? (blockIdx.x - 64) : blockIdx.x;
    const int j0 = jblk * 16;

    const __half* Bm = role ? g_B1 : g_B0;
    const int Kdim  = role ? 2048 : 1536;
    const int NC    = Kdim >> 6;
    const int SPLIT = role ? 16 : 8;        // K-chunk boundary input|hidden
    const float* b_ih = role ? bih1 : bih0;
    const float* b_hh = role ? bhh1 : bhh0;

    // ---- one-time: weights -> SMEM (swizzled chunk layout) ----
    __half* Wsm = (__half*)(smraw + SM_W_OFF);
    {
        int row = tid >> 3, c16 = tid & 7;   // 384 threads = 48 rows x 8 col16s
        size_t grow = (size_t)((row >> 4) * HID + j0 + (row & 15));
        for (int c = 0; c < NC; c++)
            cp_async16(Wsm + c * W_CHUNK_HALFS + row * 64 + ((c16 ^ (row & 7)) << 3),
                       Bm + grow * Kdim + c * 64 + c16 * 8);
        asm volatile("cp.async.commit_group;\n" ::: "memory");
        asm volatile("cp.async.wait_group 0;\n" ::: "memory");
        __syncthreads();
    }

    float* epGi = (float*)smraw;            // [64][48] overlays A stages post-loop
    float* epGh = epGi + 64 * 48;           // exactly fills 24576 B

    for (int w = 0; w <= TSTEPS; w++) {
        bool active = role ? (w >= 1) : (w < TSTEPS);
        if (active) {
            const int t = role ? (w - 1) : w;
            const int p = t & 1;
            const __half *A0, *A1;
            const float* h_old; float* hnf; __half* hnh; float* hids;
            int sA0, kA0;
            if (role == 0) {
                A0 = g_X + (size_t)t * NB * EMB; sA0 = EMB; kA0 = EMB;
                A1 = g_h0h[p];
                h_old = g_h0f[p]; hnf = g_h0f[p ^ 1]; hnh = g_h0h[p ^ 1]; hids = nullptr;
            } else {
                A0 = g_h0h[p ^ 1]; sA0 = HID; kA0 = HID;
                A1 = g_h1h[p];
                h_old = g_h1f[p]; hnf = g_h1f[p ^ 1]; hnh = g_h1h[p ^ 1];
                hids = out + (size_t)t * HID;
            }

            float accA[2][4] = {};
            float accB[2][4] = {};

            load_A(0, 0, tid, A0, sA0, kA0, A1, smraw);
            load_A(1, 1, tid, A0, sA0, kA0, A1, smraw);

            int slot = 0;
            for (int c = 0; c < NC; c++) {
                if (c + 1 < NC) asm volatile("cp.async.wait_group 1;\n" ::: "memory");
                else            asm volatile("cp.async.wait_group 0;\n" ::: "memory");
                __syncthreads();

                const __half* bA = (const __half*)smraw + slot * A_STAGE_HALFS;
                const __half* bB = Wsm + c * W_CHUNK_HALFS;
                float (*acc)[4] = (c < SPLIT) ? accA : accB;
                const int arow = wm * 16 + (lane & 15);
                const int brow = ng * 16 + (lane & 15);
                #pragma unroll
                for (int ks = 0; ks < 4; ks++) {
                    int c16 = ks * 2 + (lane >> 4);
                    uint32_t a0, a1, a2, a3;
                    ldsm4(a0, a1, a2, a3, bA + arow * 64 + ((c16 ^ (arow & 7)) << 3));
                    uint32_t r0, r1, r2, r3;
                    ldsm4(r0, r1, r2, r3, bB + brow * 64 + ((c16 ^ (brow & 7)) << 3));
                    mma_fp16(acc[0], a0, a1, a2, a3, r0, r2);
                    mma_fp16(acc[1], a0, a1, a2, a3, r1, r3);
                }

                if (c + 2 < NC) {
                    int ns = slot + 2; if (ns >= NSTAGE) ns -= NSTAGE;
                    load_A(c + 2, ns, tid, A0, sA0, kA0, A1, smraw);
                }
                if (++slot == NSTAGE) slot = 0;
            }
            __syncthreads();   // all stage reads done before ep overlay

            // ---- epilogue: accumulators -> smem (disjoint (wm, ng) slices) ----
            #pragma unroll
            for (int nt = 0; nt < 2; nt++) {
                int col = ng * 16 + nt * 8 + (lane & 3) * 2;
                int m0 = wm * 16 + (lane >> 2);
                epGi[m0 * 48 + col]           = accA[nt][0];
                epGi[m0 * 48 + col + 1]       = accA[nt][1];
                epGi[(m0 + 8) * 48 + col]     = accA[nt][2];
                epGi[(m0 + 8) * 48 + col + 1] = accA[nt][3];
                epGh[m0 * 48 + col]           = accB[nt][0];
                epGh[m0 * 48 + col + 1]       = accB[nt][1];
                epGh[(m0 + 8) * 48 + col]     = accB[nt][2];
                epGh[(m0 + 8) * 48 + col + 1] = accB[nt][3];
            }
            __syncthreads();

            // ---- GRU gate math + state write ----
            #pragma unroll
            for (int it = 0; it < 3; it++) {
                int e = tid + it * 384;
                if (e < 1024) {
                    int bm = e >> 4, u = e & 15;
                    int j = j0 + u;
                    float gir = epGi[bm * 48 + u]      + b_ih[j];
                    float giz = epGi[bm * 48 + 16 + u] + b_ih[HID + j];
                    float gin = epGi[bm * 48 + 32 + u] + b_ih[2 * HID + j];
                    float ghr = epGh[bm * 48 + u]      + b_hh[j];
                    float ghz = epGh[bm * 48 + 16 + u] + b_hh[HID + j];
                    float ghn = epGh[bm * 48 + 32 + u] + b_hh[2 * HID + j];
                    float r = 1.0f / (1.0f + __expf(-(gir + ghr)));
                    float z = 1.0f / (1.0f + __expf(-(giz + ghz)));
                    float n = tanhf(gin + r * ghn);
                    float h = (1.0f - z) * n + z * h_old[bm * HID + j];
                    hnf[bm * HID + j] = h;
                    hnh[bm * HID + j] = __float2half(h);
                    if (hids) hids[(size_t)bm * TSTEPS * HID + j] = h;  // dec_hids[n][t][:]
                }
            }
        }
        grid_bar(128 * (w + 1));
    }
}

// -------- launcher (graph-capturable: kernel launches only) --------
extern "C" void kernel_launch(void* const* d_in, const int* in_sizes, int n_in,
                              void* d_out, int out_size) {
    const int*   tokens   = (const int*)d_in[0];
    const float* dec_init = (const float*)d_in[1];
    const float* emb      = (const float*)d_in[2];
    const float* Wih0     = (const float*)d_in[3];
    const float* Whh0     = (const float*)d_in[4];
    const float* bih0     = (const float*)d_in[5];
    const float* bhh0     = (const float*)d_in[6];
    const float* Wih1     = (const float*)d_in[7];
    const float* Whh1     = (const float*)d_in[8];
    const float* bih1     = (const float*)d_in[9];
    const float* bhh1     = (const float*)d_in[10];
    float* out = (float*)d_out;

    cudaFuncSetAttribute(k_run, cudaFuncAttributeMaxDynamicSharedMemorySize, SM_TOTAL);

    k_init<<<64, 256>>>(dec_init);
    k_pack<<<512, 256>>>(Wih0, Whh0, Wih1, Whh1);
    k_embed<<<TSTEPS * NB, 128>>>(tokens, emb);

    k_run<<<128, 384, SM_TOTAL>>>(bih0, bhh0, bih1, bhh1, out);

    k_final<<<64, 256>>>(out);
}